// round 16
// baseline (speedup 1.0000x reference)
#include <cuda_runtime.h>
#include <cuda_fp16.h>
#include <math.h>
#include <cstdint>

#define B_    8
#define T_    1024
#define DIM_  2048
#define H_    16
#define NKV_  4
#define HD_   128
#define KVD_  512
#define SCALE_ 0.08838834764831845f
#define EPS_  1e-6f

// ---------------- scratch ------------------------------------------------------
__device__ float g_v[B_*T_*KVD_];
__device__ float g_rope[T_*64*2];
__device__ __half g_xh[B_*T_*DIM_];
__device__ __half g_xl[B_*T_*DIM_];
__device__ __half g_wq[DIM_*DIM_];
__device__ __half g_wk[KVD_*DIM_];
__device__ __half g_wv[KVD_*DIM_];
__device__ __half g_wp[DIM_*DIM_];
__device__ __half g_qh[B_*T_*DIM_];
__device__ __half g_ql[B_*T_*DIM_];
__device__ __half g_kh[B_*T_*KVD_];
__device__ __half g_vth[B_*NKV_*HD_*T_];

// ---------------- helpers ------------------------------------------------------
__device__ __forceinline__ uint32_t smem_u32(const void* p) {
  uint32_t a;
  asm("{ .reg .u64 t; cvta.to.shared.u64 t, %1; cvt.u32.u64 %0, t; }" : "=r"(a) : "l"(p));
  return a;
}
#define CP_ASYNC16(dst, src) \
  asm volatile("cp.async.cg.shared.global [%0], [%1], 16;" :: "r"(dst), "l"(src))
#define CP_COMMIT() asm volatile("cp.async.commit_group;" ::: "memory")
#define CP_WAIT1() asm volatile("cp.async.wait_group 1;" ::: "memory")
#define CP_WAIT0() asm volatile("cp.async.wait_group 0;" ::: "memory")

__device__ __forceinline__ void ldsm4(uint32_t* r, uint32_t addr) {
  asm volatile("ldmatrix.sync.aligned.m8n8.x4.shared.b16 {%0,%1,%2,%3}, [%4];"
               : "=r"(r[0]), "=r"(r[1]), "=r"(r[2]), "=r"(r[3]) : "r"(addr));
}
__device__ __forceinline__ void mma_f16(float* d, const uint32_t* a, const uint32_t* b) {
  asm volatile("mma.sync.aligned.m16n8k16.row.col.f32.f16.f16.f32 "
               "{%0,%1,%2,%3}, {%4,%5,%6,%7}, {%8,%9}, {%0,%1,%2,%3};"
               : "+f"(d[0]), "+f"(d[1]), "+f"(d[2]), "+f"(d[3])
               : "r"(a[0]), "r"(a[1]), "r"(a[2]), "r"(a[3]), "r"(b[0]), "r"(b[1]));
}
__device__ __forceinline__ uint32_t pack_h2(float a, float b) {
  __half2 p{__float2half_rn(a), __float2half_rn(b)};
  return *(uint32_t*)&p;
}

// ---------------- RoPE table precompute ----------------------------------------
__global__ void rope_table_kernel() {
  int idx = blockIdx.x * blockDim.x + threadIdx.x;
  if (idx >= T_ * 64) return;
  int t = idx >> 6, j = idx & 63;
  const double lg = 9.210340371976184;
  float inv = (float)exp(-(double)j / 64.0 * lg);
  float f = (float)t * inv;
  double s, c;
  sincos((double)f, &s, &c);
  g_rope[idx * 2]     = (float)c;
  g_rope[idx * 2 + 1] = (float)s;
}

// ---------------- f32 -> fp16 hi/lo split (2 planes) ---------------------------
__global__ __launch_bounds__(256) void split2_kernel(const float* __restrict__ X,
                                                     __half* __restrict__ Hh,
                                                     __half* __restrict__ Ll, int n4) {
  int i = blockIdx.x * blockDim.x + threadIdx.x;
  if (i >= n4) return;
  float4 v = *(const float4*)(X + (size_t)i * 4);
  __half h0 = __float2half_rn(v.x), h1 = __float2half_rn(v.y);
  __half h2 = __float2half_rn(v.z), h3 = __float2half_rn(v.w);
  __half2 hp0{h0, h1}, hp1{h2, h3};
  __half2 lp0{__float2half_rn(v.x - __half2float(h0)), __float2half_rn(v.y - __half2float(h1))};
  __half2 lp1{__float2half_rn(v.z - __half2float(h2)), __float2half_rn(v.w - __half2float(h3))};
  *(uint2*)(Hh + (size_t)i * 4) = make_uint2(*(uint32_t*)&hp0, *(uint32_t*)&hp1);
  *(uint2*)(Ll + (size_t)i * 4) = make_uint2(*(uint32_t*)&lp0, *(uint32_t*)&lp1);
}

// ---------------- all four weight truncations in one launch --------------------
#define N4_WQ (DIM_*DIM_/4)
#define N4_WK (KVD_*DIM_/4)
__global__ __launch_bounds__(256) void trunc_all_kernel(
    const float* __restrict__ Wq, const float* __restrict__ Wk,
    const float* __restrict__ Wv, const float* __restrict__ Wp,
    __half* __restrict__ wq, __half* __restrict__ wk,
    __half* __restrict__ wv, __half* __restrict__ wp) {
  int i = blockIdx.x * blockDim.x + threadIdx.x;
  const float* src; __half* dst; int off;
  if (i < N4_WQ)                     { src = Wq; dst = wq; off = i; }
  else if (i < N4_WQ + N4_WK)        { src = Wk; dst = wk; off = i - N4_WQ; }
  else if (i < N4_WQ + 2 * N4_WK)    { src = Wv; dst = wv; off = i - N4_WQ - N4_WK; }
  else                               { src = Wp; dst = wp; off = i - N4_WQ - 2 * N4_WK; }
  float4 v = *(const float4*)(src + (size_t)off * 4);
  __half2 hp0{__float2half_rn(v.x), __float2half_rn(v.y)};
  __half2 hp1{__float2half_rn(v.z), __float2half_rn(v.w)};
  *(uint2*)(dst + (size_t)off * 4) = make_uint2(*(uint32_t*)&hp0, *(uint32_t*)&hp1);
}

// ---------------- merged Q/K/V HMMA GEMM (one launch) --------------------------
#define GT (128 * 64 * 2)
#define SMEM_HG (2 * 3 * GT)              // 96KB
#define TSTR 134

__global__ __launch_bounds__(256, 2) void gemm_qkv(
    const __half* __restrict__ Ah, const __half* __restrict__ Al,
    const __half* __restrict__ Wq, const __half* __restrict__ Wk,
    const __half* __restrict__ Wv,
    __half* __restrict__ Qh, __half* __restrict__ Ql, __half* __restrict__ Kh,
    float* __restrict__ Vf, __half* __restrict__ Vt,
    const float* __restrict__ gain) {
  extern __shared__ char sm[];
  const uint32_t sb = smem_u32(sm);
  const int tid = threadIdx.x;
  const int l = tid & 31, w = tid >> 5;
  const int gx = blockIdx.x;
  const int bm = blockIdx.y * 128;
  const int wm = (w & 1) * 64, wn = (w >> 1) * 32;
  const int K = DIM_;

  int mode, bn;
  const __half* Bp;
  int N;
  if (gx < 16)      { mode = 0; bn = gx * 128;        Bp = Wq; N = DIM_; }
  else if (gx < 20) { mode = 1; bn = (gx - 16) * 128; Bp = Wk; N = KVD_; }
  else              { mode = 2; bn = (gx - 20) * 128; Bp = Wv; N = KVD_; }

  int ldrow[4]; uint32_t lddst[4]; int ldkoff[4];
#pragma unroll
  for (int s = 0; s < 4; s++) {
    int ch = tid + s * 256;
    ldrow[s] = ch >> 3;
    int kcol = ch & 7;
    lddst[s] = (uint32_t)(ldrow[s] * 128 + ((kcol * 16) ^ ((ldrow[s] & 7) << 4)));
    ldkoff[s] = kcol;
  }
  const int arow = (l & 7) + ((l >> 3) & 1) * 8;
  const int akb  = (l >> 4) * 16;
  const int brow = (l & 7) + (l >> 4) * 8;
  const int bkb  = ((l >> 3) & 1) * 16;
  const int kxor = (l & 7) << 4;
  int aoff[4], boff[2];
#pragma unroll
  for (int i = 0; i < 4; i++) aoff[i] = (wm + i * 16 + arow) * 128;
#pragma unroll
  for (int j = 0; j < 2; j++) boff[j] = (wn + j * 16 + brow) * 128;

  float acc[4][4][4];
#pragma unroll
  for (int i = 0; i < 4; i++)
#pragma unroll
    for (int j = 0; j < 4; j++)
#pragma unroll
      for (int r = 0; r < 4; r++) acc[i][j][r] = 0.f;

  const int NC = K / 64;

#define ISSUE_CHUNK(cc, buf) do {                                              \
    uint32_t base = sb + (buf) * 3 * GT;                                       \
    const __half* srcs[3] = {Ah, Al, Bp};                                      \
    _Pragma("unroll")                                                          \
    for (int tile = 0; tile < 3; tile++) {                                     \
      int rb = (tile < 2) ? bm : bn;                                           \
      const __half* sp = srcs[tile];                                           \
      _Pragma("unroll")                                                        \
      for (int s = 0; s < 4; s++) {                                            \
        const __half* src = sp + (size_t)(rb + ldrow[s]) * K +                 \
                            (cc) * 64 + ldkoff[s] * 8;                         \
        CP_ASYNC16(base + tile * GT + lddst[s], src);                          \
      }                                                                        \
    }                                                                          \
    CP_COMMIT();                                                               \
  } while (0)

  ISSUE_CHUNK(0, 0);

  for (int c = 0; c < NC; c++) {
    const int buf = c & 1;
    if (c + 1 < NC) { ISSUE_CHUNK(c + 1, buf ^ 1); CP_WAIT1(); }
    else            { CP_WAIT0(); }
    __syncthreads();

    const uint32_t tb = sb + buf * 3 * GT;
#pragma unroll
    for (int kc = 0; kc < 4; kc++) {
      uint32_t ah[4][4], al[4][4], bh[2][4];
      const uint32_t kA = (uint32_t)((kc * 32 + akb) ^ kxor);
      const uint32_t kB = (uint32_t)((kc * 32 + bkb) ^ kxor);
#pragma unroll
      for (int i = 0; i < 4; i++) {
        ldsm4(ah[i], tb + aoff[i] + kA);
        ldsm4(al[i], tb + GT + aoff[i] + kA);
      }
#pragma unroll
      for (int j = 0; j < 2; j++)
        ldsm4(bh[j], tb + 2 * GT + boff[j] + kB);
#pragma unroll
      for (int i = 0; i < 4; i++)
#pragma unroll
        for (int jf = 0; jf < 4; jf++) {
          const uint32_t* bph = &bh[jf >> 1][(jf & 1) * 2];
          mma_f16(acc[i][jf], ah[i], bph);
          mma_f16(acc[i][jf], al[i], bph);
        }
    }
    __syncthreads();
  }
#undef ISSUE_CHUNK

  const int r0 = bm + wm + (l >> 2);
  const int c0 = bn + wn + (l & 3) * 2;

  if (mode == 2) {
#pragma unroll
    for (int i = 0; i < 4; i++)
#pragma unroll
      for (int j = 0; j < 4; j++) {
        float* p0 = Vf + (size_t)(r0 + i * 16) * N + c0 + j * 8;
        float* p1 = Vf + (size_t)(r0 + i * 16 + 8) * N + c0 + j * 8;
        *(float2*)p0 = make_float2(acc[i][j][0], acc[i][j][1]);
        *(float2*)p1 = make_float2(acc[i][j][2], acc[i][j][3]);
      }
  }

  float* tile = (float*)sm;
  const int rl = wm + (l >> 2);
  const int cl = wn + (l & 3) * 2;
#pragma unroll
  for (int i = 0; i < 4; i++)
#pragma unroll
    for (int j = 0; j < 4; j++) {
      tile[(rl + i * 16) * TSTR + cl + j * 8]     = acc[i][j][0];
      tile[(rl + i * 16) * TSTR + cl + j * 8 + 1] = acc[i][j][1];
      tile[(rl + i * 16 + 8) * TSTR + cl + j * 8]     = acc[i][j][2];
      tile[(rl + i * 16 + 8) * TSTR + cl + j * 8 + 1] = acc[i][j][3];
    }
  __syncthreads();

  if (mode < 2) {
    const float gn = (mode == 0) ? gain[bn >> 7] : 1.f;
    __half* Oh = (mode == 0) ? Qh : Kh;
    __half* Ol = (mode == 0) ? Ql : nullptr;
#pragma unroll 1
    for (int it = 0; it < 16; it++) {
      int r = w * 16 + it;
      int grow = bm + r;
      int t = grow & (T_ - 1);
      float2 x1 = *(float2*)&tile[r * TSTR + l * 2];
      float2 x2 = *(float2*)&tile[r * TSTR + 64 + l * 2];
      float ss = x1.x*x1.x + x1.y*x1.y + x2.x*x2.x + x2.y*x2.y;
#pragma unroll
      for (int o = 16; o > 0; o >>= 1) ss += __shfl_xor_sync(0xffffffffu, ss, o);
      float gm = gn * rsqrtf(ss * (1.f / HD_) + EPS_);
      x1.x *= gm; x1.y *= gm; x2.x *= gm; x2.y *= gm;
      float4 cs = *(const float4*)(g_rope + (size_t)t * 128 + l * 4);
      float o1x = x1.x * cs.x - x2.x * cs.y;
      float o1y = x1.y * cs.z - x2.y * cs.w;
      float o2x = x2.x * cs.x + x1.x * cs.y;
      float o2y = x2.y * cs.z + x1.y * cs.w;
      size_t base = (size_t)grow * N + bn;
      __half h1a = __float2half_rn(o1x), h1b = __float2half_rn(o1y);
      __half h2a = __float2half_rn(o2x), h2b = __float2half_rn(o2y);
      __half2 hp1{h1a, h1b}, hp2{h2a, h2b};
      *(uint32_t*)(Oh + base + l * 2)      = *(uint32_t*)&hp1;
      *(uint32_t*)(Oh + base + 64 + l * 2) = *(uint32_t*)&hp2;
      if (Ol != nullptr) {
        __half2 lp1{__float2half_rn(o1x - __half2float(h1a)),
                    __float2half_rn(o1y - __half2float(h1b))};
        __half2 lp2{__float2half_rn(o2x - __half2float(h2a)),
                    __float2half_rn(o2y - __half2float(h2b))};
        *(uint32_t*)(Ol + base + l * 2)      = *(uint32_t*)&lp1;
        *(uint32_t*)(Ol + base + 64 + l * 2) = *(uint32_t*)&lp2;
      }
    }
  } else {
    const int b = bm >> 10, t0 = bm & (T_ - 1);
    const int kv = bn >> 7;
    const size_t vbase = ((size_t)(b * NKV_ + kv) * HD_) * T_;
#pragma unroll 1
    for (int it = 0; it < 16; it++) {
      int d = w * 16 + it;
      float v0 = tile[(l * 4 + 0) * TSTR + d];
      float v1 = tile[(l * 4 + 1) * TSTR + d];
      float v2 = tile[(l * 4 + 2) * TSTR + d];
      float v3 = tile[(l * 4 + 3) * TSTR + d];
      __half2 p0{__float2half_rn(v0), __float2half_rn(v1)};
      __half2 p1{__float2half_rn(v2), __float2half_rn(v3)};
      *(uint2*)(Vt + vbase + (size_t)d * T_ + t0 + l * 4) =
          make_uint2(*(uint32_t*)&p0, *(uint32_t*)&p1);
    }
  }
}

// ---------------- proj GEMM: 128x256 tile, single A-plane ----------------------
// buffer: [A 16KB][B 32KB] = 48KB, x2 = 96KB -> 2 CTA/SM
#define PBUF 49152
#define SMEM_PJ (2 * PBUF)

__global__ __launch_bounds__(256, 2) void gemm_proj(
    const __half* __restrict__ Ah, const __half* __restrict__ Bh,
    float* __restrict__ C, int N, int K) {
  extern __shared__ char sm[];
  const uint32_t sb = smem_u32(sm);
  const int tid = threadIdx.x;
  const int l = tid & 31, w = tid >> 5;
  const int bm = blockIdx.y * 128, bn = blockIdx.x * 256;
  const int wm = (w & 1) * 64, wn = (w >> 1) * 64;

  const int arow = (l & 7) + ((l >> 3) & 1) * 8;
  const int akb  = (l >> 4) * 16;
  const int brow = (l & 7) + (l >> 4) * 8;
  const int bkb  = ((l >> 3) & 1) * 16;
  const int kxor = (l & 7) << 4;
  int aoff[4];
#pragma unroll
  for (int i = 0; i < 4; i++) aoff[i] = (wm + i * 16 + arow) * 128;

  float acc[4][8][4];
#pragma unroll
  for (int i = 0; i < 4; i++)
#pragma unroll
    for (int j = 0; j < 8; j++)
#pragma unroll
      for (int r = 0; r < 4; r++) acc[i][j][r] = 0.f;

  const int NC = K / 64;

#define ISSUE_P(cc, buf) do {                                                  \
    uint32_t base = sb + (buf) * PBUF;                                         \
    _Pragma("unroll")                                                          \
    for (int s = 0; s < 4; s++) {                                              \
      int ch = tid + s * 256;                                                  \
      int r = ch >> 3, c8 = ch & 7;                                            \
      uint32_t dst = (uint32_t)(r * 128 + ((c8 * 16) ^ ((r & 7) << 4)));       \
      CP_ASYNC16(base + dst, Ah + (size_t)(bm + r) * K + (cc) * 64 + c8 * 8);  \
    }                                                                          \
    _Pragma("unroll")                                                          \
    for (int s = 0; s < 8; s++) {                                              \
      int ch = tid + s * 256;                                                  \
      int r = ch >> 3, c8 = ch & 7;                                            \
      uint32_t dst = (uint32_t)(r * 128 + ((c8 * 16) ^ ((r & 7) << 4)));       \
      CP_ASYNC16(base + 16384 + dst,                                           \
                 Bh + (size_t)(bn + r) * K + (cc) * 64 + c8 * 8);              \
    }                                                                          \
    CP_COMMIT();                                                               \
  } while (0)

  ISSUE_P(0, 0);

  for (int c = 0; c < NC; c++) {
    const int buf = c & 1;
    if (c + 1 < NC) { ISSUE_P(c + 1, buf ^ 1); CP_WAIT1(); }
    else            { CP_WAIT0(); }
    __syncthreads();

    const uint32_t tb = sb + buf * PBUF;
#pragma unroll
    for (int kc = 0; kc < 4; kc++) {
      const uint32_t kA = (uint32_t)((kc * 32 + akb) ^ kxor);
      const uint32_t kB = (uint32_t)((kc * 32 + bkb) ^ kxor);
      uint32_t ah[4][4];
#pragma unroll
      for (int i = 0; i < 4; i++) ldsm4(ah[i], tb + aoff[i] + kA);
#pragma unroll
      for (int jg = 0; jg < 4; jg++) {
        uint32_t bh4[4];
        ldsm4(bh4, tb + 16384 + (wn + jg * 16 + brow) * 128 + kB);
#pragma unroll
        for (int i = 0; i < 4; i++) {
          mma_f16(acc[i][2 * jg],     ah[i], &bh4[0]);
          mma_f16(acc[i][2 * jg + 1], ah[i], &bh4[2]);
        }
      }
    }
    __syncthreads();
  }
#undef ISSUE_P

  const int r0 = bm + wm + (l >> 2);
  const int c0 = bn + wn + (l & 3) * 2;
#pragma unroll
  for (int i = 0; i < 4; i++)
#pragma unroll
    for (int j = 0; j < 8; j++) {
      float* p0 = C + (size_t)(r0 + i * 16) * N + c0 + j * 8;
      float* p1 = C + (size_t)(r0 + i * 16 + 8) * N + c0 + j * 8;
      *(float2*)p0 = make_float2(acc[i][j][0], acc[i][j][1]);
      *(float2*)p1 = make_float2(acc[i][j][2], acc[i][j][3]);
    }
}

// ---------------- HMMA flash attention + fused v-rejection + trunc -------------
#define FQ_OFF   0
#define FBUF_OFF 65536
#define SMEM_FLA (65536 + 2 * 32768)
#define VSTR 136

__global__ __launch_bounds__(256, 1) void flash_hmma(
    const __half* __restrict__ Qh, const __half* __restrict__ Ql,
    const __half* __restrict__ Kh, const __half* __restrict__ Vth,
    const float* __restrict__ Vf,
    __half* __restrict__ Yh) {
  extern __shared__ char sm[];
  const uint32_t sb = smem_u32(sm);
  const int tid = threadIdx.x;
  const int l = tid & 31, w = tid >> 5;
  const int qtile = gridDim.x - 1 - blockIdx.x;
  const int bh = blockIdx.y;
  const int b = bh >> 4, h = bh & 15, kv = h >> 2;
  const int q0 = qtile * 128;
  const int wm = w * 16;

  const int arow = (l & 7) + ((l >> 3) & 1) * 8;
  const int akb  = (l >> 4) * 16;
  const int brow = (l & 7) + (l >> 4) * 8;
  const int bkb  = ((l >> 3) & 1) * 16;
  const uint32_t kxA = (uint32_t)((l & 7) << 4);

#pragma unroll
  for (int s = 0; s < 8; s++) {
    int ch = tid + s * 256;
    int kchunk = ch >> 10;
    int cid = ch & 1023;
    int r = cid >> 3, cc = cid & 7;
    uint32_t dst = (uint32_t)(kchunk * 16384 + r * 128 + ((cc * 16) ^ ((r & 7) << 4)));
    size_t src = (size_t)(b * T_ + q0 + r) * DIM_ + h * HD_ + kchunk * 64 + cc * 8;
    CP_ASYNC16(sb + FQ_OFF + dst, Qh + src);
    CP_ASYNC16(sb + FQ_OFF + 32768 + dst, Ql + src);
  }
  CP_COMMIT();

#define FKV_ISSUE(tt, buf) do {                                                 \
    uint32_t base = sb + FBUF_OFF + (buf) * 32768;                              \
    int s0_ = (tt) * 64;                                                        \
    _Pragma("unroll")                                                           \
    for (int s = 0; s < 4; s++) {                                               \
      int ch = tid + s * 256;                                                   \
      int kchunk = ch >> 9;                                                     \
      int cid = ch & 511;                                                       \
      int r = cid >> 3, cc = cid & 7;                                           \
      uint32_t dst = (uint32_t)(kchunk * 8192 + r * 128 +                       \
                                ((cc * 16) ^ ((r & 7) << 4)));                  \
      size_t src = (size_t)(b * T_ + s0_ + r) * KVD_ + kv * 128 +               \
                   kchunk * 64 + cc * 8;                                        \
      CP_ASYNC16(base + dst, Kh + src);                                         \
    }                                                                           \
    _Pragma("unroll")                                                           \
    for (int s = 0; s < 4; s++) {                                               \
      int ch = tid + s * 256;                                                   \
      int r = ch >> 3, cc = ch & 7;                                             \
      uint32_t dst = (uint32_t)(r * 128 + ((cc * 16) ^ ((r & 7) << 4)));        \
      size_t src = ((size_t)(b * 4 + kv) * 128 + r) * T_ + s0_ + cc * 8;        \
      CP_ASYNC16(base + 16384 + dst, Vth + src);                                \
    }                                                                           \
    CP_COMMIT();                                                                \
  } while (0)

  const int nt = (q0 + 128) / 64;
  FKV_ISSUE(0, 0);

  float ys[16][4];
#pragma unroll
  for (int i = 0; i < 16; i++)
#pragma unroll
    for (int r = 0; r < 4; r++) ys[i][r] = 0.f;
  float m0 = -INFINITY, m1 = -INFINITY, l0 = 0.f, l1 = 0.f;
  const int rg0 = q0 + wm + (l >> 2);
  const int wrow_max = q0 + wm + 15;

  for (int t = 0; t < nt; t++) {
    const int buf = t & 1;
    if (t + 1 < nt) { FKV_ISSUE(t + 1, buf ^ 1); CP_WAIT1(); }
    else            { CP_WAIT0(); }
    __syncthreads();

    const int s0 = t * 64;
    if (s0 <= wrow_max) {
      const uint32_t KB = sb + FBUF_OFF + buf * 32768;
      const uint32_t VB = KB + 16384;
      float sacc[8][4];
#pragma unroll
      for (int j = 0; j < 8; j++)
#pragma unroll
        for (int r = 0; r < 4; r++) sacc[j][r] = 0.f;

#pragma unroll
      for (int ks = 0; ks < 8; ks++) {
        const int kchunk = ks >> 2, kc = ks & 3;
        uint32_t ah[4], al[4];
        uint32_t qa = sb + FQ_OFF + kchunk * 16384 + (wm + arow) * 128 +
                      (((kc * 32 + akb)) ^ kxA);
        ldsm4(ah, qa);
        ldsm4(al, qa + 32768);
#pragma unroll
        for (int j = 0; j < 4; j++) {
          uint32_t bh4[4];
          uint32_t ka = KB + kchunk * 8192 + (j * 16 + brow) * 128 +
                        (((kc * 32 + bkb)) ^ kxA);
          ldsm4(bh4, ka);
          mma_f16(sacc[2 * j],     ah, &bh4[0]);
          mma_f16(sacc[2 * j],     al, &bh4[0]);
          mma_f16(sacc[2 * j + 1], ah, &bh4[2]);
          mma_f16(sacc[2 * j + 1], al, &bh4[2]);
        }
      }

#pragma unroll
      for (int j = 0; j < 8; j++) {
        int cg = s0 + j * 8 + (l & 3) * 2;
        sacc[j][0] = (cg     <= rg0)     ? sacc[j][0] * SCALE_ : -INFINITY;
        sacc[j][1] = (cg + 1 <= rg0)     ? sacc[j][1] * SCALE_ : -INFINITY;
        sacc[j][2] = (cg     <= rg0 + 8) ? sacc[j][2] * SCALE_ : -INFINITY;
        sacc[j][3] = (cg + 1 <= rg0 + 8) ? sacc[j][3] * SCALE_ : -INFINITY;
      }
      float rm0 = -INFINITY, rm1 = -INFINITY;
#pragma unroll
      for (int j = 0; j < 8; j++) {
        rm0 = fmaxf(rm0, fmaxf(sacc[j][0], sacc[j][1]));
        rm1 = fmaxf(rm1, fmaxf(sacc[j][2], sacc[j][3]));
      }
      rm0 = fmaxf(rm0, __shfl_xor_sync(0xffffffffu, rm0, 1));
      rm0 = fmaxf(rm0, __shfl_xor_sync(0xffffffffu, rm0, 2));
      rm1 = fmaxf(rm1, __shfl_xor_sync(0xffffffffu, rm1, 1));
      rm1 = fmaxf(rm1, __shfl_xor_sync(0xffffffffu, rm1, 2));
      float nm0 = fmaxf(m0, rm0), nm1 = fmaxf(m1, rm1);
      float a0 = expf(m0 - nm0), a1 = expf(m1 - nm1);
      m0 = nm0; m1 = nm1;
      l0 *= a0; l1 *= a1;
#pragma unroll
      for (int i = 0; i < 16; i++) {
        ys[i][0] *= a0; ys[i][1] *= a0; ys[i][2] *= a1; ys[i][3] *= a1;
      }
#pragma unroll
      for (int j = 0; j < 8; j++) {
        sacc[j][0] = expf(sacc[j][0] - nm0);
        sacc[j][1] = expf(sacc[j][1] - nm0);
        sacc[j][2] = expf(sacc[j][2] - nm1);
        sacc[j][3] = expf(sacc[j][3] - nm1);
        l0 += sacc[j][0] + sacc[j][1];
        l1 += sacc[j][2] + sacc[j][3];
      }

#pragma unroll
      for (int u = 0; u < 4; u++) {
        uint32_t pha[4];
        pha[0] = pack_h2(sacc[2*u][0], sacc[2*u][1]);
        pha[1] = pack_h2(sacc[2*u][2], sacc[2*u][3]);
        pha[2] = pack_h2(sacc[2*u+1][0], sacc[2*u+1][1]);
        pha[3] = pack_h2(sacc[2*u+1][2], sacc[2*u+1][3]);
#pragma unroll
        for (int jj = 0; jj < 8; jj++) {
          uint32_t vh4[4];
          uint32_t va = VB + (jj * 16 + brow) * 128 + (((u * 32 + bkb)) ^ kxA);
          ldsm4(vh4, va);
          mma_f16(ys[2 * jj],     pha, &vh4[0]);
          mma_f16(ys[2 * jj + 1], pha, &vh4[2]);
        }
      }
    }
    __syncthreads();
  }
#undef FKV_ISSUE

  l0 += __shfl_xor_sync(0xffffffffu, l0, 1);
  l0 += __shfl_xor_sync(0xffffffffu, l0, 2);
  l1 += __shfl_xor_sync(0xffffffffu, l1, 1);
  l1 += __shfl_xor_sync(0xffffffffu, l1, 2);
  const float i0 = 1.f / l0, i1 = 1.f / l1;

  float* vs = (float*)sm;
  __syncthreads();
#pragma unroll
  for (int s = 0; s < 16; s++) {
    int idx = tid + s * 256;
    int r = idx >> 5, c4 = (idx & 31) << 2;
    *(float4*)&vs[r * VSTR + c4] =
        *(const float4*)(Vf + (size_t)(b * T_ + q0 + r) * KVD_ + kv * 128 + c4);
  }
  __syncthreads();

  const int lr0 = wm + (l >> 2), lr1 = lr0 + 8;
  float ss0 = 0.f, ss1 = 0.f;
#pragma unroll
  for (int tt = 0; tt < 16; tt++) {
    int c = tt * 8 + (l & 3) * 2;
    float2 a = *(float2*)&vs[lr0 * VSTR + c];
    float2 bb = *(float2*)&vs[lr1 * VSTR + c];
    ss0 += a.x * a.x + a.y * a.y;
    ss1 += bb.x * bb.x + bb.y * bb.y;
  }
  ss0 += __shfl_xor_sync(0xffffffffu, ss0, 1);
  ss0 += __shfl_xor_sync(0xffffffffu, ss0, 2);
  ss1 += __shfl_xor_sync(0xffffffffu, ss1, 1);
  ss1 += __shfl_xor_sync(0xffffffffu, ss1, 2);
  const float inv0 = 1.f / (sqrtf(ss0) + 1e-8f);
  const float inv1 = 1.f / (sqrtf(ss1) + 1e-8f);

  float dot0 = 0.f, dot1 = 0.f;
#pragma unroll
  for (int tt = 0; tt < 16; tt++) {
    int c = tt * 8 + (l & 3) * 2;
    float2 a = *(float2*)&vs[lr0 * VSTR + c];
    float2 bb = *(float2*)&vs[lr1 * VSTR + c];
    ys[tt][0] *= i0; ys[tt][1] *= i0; ys[tt][2] *= i1; ys[tt][3] *= i1;
    dot0 += ys[tt][0] * a.x + ys[tt][1] * a.y;
    dot1 += ys[tt][2] * bb.x + ys[tt][3] * bb.y;
  }
  dot0 += __shfl_xor_sync(0xffffffffu, dot0, 1);
  dot0 += __shfl_xor_sync(0xffffffffu, dot0, 2);
  dot1 += __shfl_xor_sync(0xffffffffu, dot1, 1);
  dot1 += __shfl_xor_sync(0xffffffffu, dot1, 2);
  const float s0c = dot0 * inv0 * inv0;
  const float s1c = dot1 * inv1 * inv1;

#pragma unroll
  for (int tt = 0; tt < 16; tt++) {
    int c = tt * 8 + (l & 3) * 2;
    float2 a = *(float2*)&vs[lr0 * VSTR + c];
    float2 bb = *(float2*)&vs[lr1 * VSTR + c];
    float o00 = ys[tt][0] - s0c * a.x;
    float o01 = ys[tt][1] - s0c * a.y;
    float o10 = ys[tt][2] - s1c * bb.x;
    float o11 = ys[tt][3] - s1c * bb.y;
    size_t off0 = (size_t)(b * T_ + rg0) * DIM_ + h * HD_ + c;
    size_t off1 = (size_t)(b * T_ + rg0 + 8) * DIM_ + h * HD_ + c;
    __half2 hp0{__float2half_rn(o00), __float2half_rn(o01)};
    __half2 hp1{__float2half_rn(o10), __float2half_rn(o11)};
    *(uint32_t*)(Yh + off0) = *(uint32_t*)&hp0;
    *(uint32_t*)(Yh + off1) = *(uint32_t*)&hp1;
  }
}

// ---------------- launch ------------------------------------------------------
extern "C" void kernel_launch(void* const* d_in, const int* in_sizes, int n_in,
                              void* d_out, int out_size) {
  const float* x     = (const float*)d_in[0];
  const float* Wq    = (const float*)d_in[1];
  const float* Wk    = (const float*)d_in[2];
  const float* Wv    = (const float*)d_in[3];
  const float* Wproj = (const float*)d_in[4];
  const float* qgain = (const float*)d_in[5];
  float* out = (float*)d_out;

  float *vb;
  cudaGetSymbolAddress((void**)&vb, g_v);
  __half *xh, *xl, *wq, *wk, *wv, *wp, *qh, *ql, *kh, *vth;
  cudaGetSymbolAddress((void**)&xh, g_xh);
  cudaGetSymbolAddress((void**)&xl, g_xl);
  cudaGetSymbolAddress((void**)&wq, g_wq);
  cudaGetSymbolAddress((void**)&wk, g_wk);
  cudaGetSymbolAddress((void**)&wv, g_wv);
  cudaGetSymbolAddress((void**)&wp, g_wp);
  cudaGetSymbolAddress((void**)&qh, g_qh);
  cudaGetSymbolAddress((void**)&ql, g_ql);
  cudaGetSymbolAddress((void**)&kh, g_kh);
  cudaGetSymbolAddress((void**)&vth, g_vth);

  cudaFuncSetAttribute((void*)gemm_qkv, cudaFuncAttributeMaxDynamicSharedMemorySize, SMEM_HG);
  cudaFuncSetAttribute((void*)gemm_proj, cudaFuncAttributeMaxDynamicSharedMemorySize, SMEM_PJ);
  cudaFuncSetAttribute((void*)flash_hmma, cudaFuncAttributeMaxDynamicSharedMemorySize, SMEM_FLA);

  const int M = B_ * T_;

  rope_table_kernel<<<(T_ * 64 + 255) / 256, 256>>>();
  split2_kernel<<<(M * DIM_ / 4 + 255) / 256, 256>>>(x, xh, xl, M * DIM_ / 4);
  const int n4all = 2 * N4_WQ + 2 * N4_WK;
  trunc_all_kernel<<<(n4all + 255) / 256, 256>>>(Wq, Wk, Wv, Wproj, wq, wk, wv, wp);

  dim3 gqkv(24, M / 128);
  gemm_qkv<<<gqkv, 256, SMEM_HG>>>(xh, xl, wq, wk, wv, qh, ql, kh, vb, vth, qgain);

  dim3 gf(T_ / 128, B_ * H_);
  flash_hmma<<<gf, 256, SMEM_FLA>>>(qh, ql, kh, vth, vb, xh);

  dim3 gwide(DIM_ / 256, M / 128);   // (8, 64)
  gemm_proj<<<gwide, 256, SMEM_PJ>>>(xh, wp, out, DIM_, DIM_);
}

// round 17
// speedup vs baseline: 1.4162x; 1.4162x over previous
#include <cuda_runtime.h>
#include <cuda_fp16.h>
#include <math.h>
#include <cstdint>

#define B_    8
#define T_    1024
#define DIM_  2048
#define H_    16
#define NKV_  4
#define HD_   128
#define KVD_  512
#define SCALE_ 0.08838834764831845f
#define EPS_  1e-6f

// ---------------- scratch ------------------------------------------------------
__device__ float g_v[B_*T_*KVD_];
__device__ float g_rope[T_*64*2];
__device__ __half g_xh[B_*T_*DIM_];
__device__ __half g_xl[B_*T_*DIM_];
__device__ __half g_wq[DIM_*DIM_];
__device__ __half g_wk[KVD_*DIM_];
__device__ __half g_wv[KVD_*DIM_];
__device__ __half g_wp[DIM_*DIM_];
__device__ __half g_qh[B_*T_*DIM_];
__device__ __half g_ql[B_*T_*DIM_];
__device__ __half g_kh[B_*T_*KVD_];
__device__ __half g_vth[B_*NKV_*HD_*T_];

// ---------------- helpers ------------------------------------------------------
__device__ __forceinline__ uint32_t smem_u32(const void* p) {
  uint32_t a;
  asm("{ .reg .u64 t; cvta.to.shared.u64 t, %1; cvt.u32.u64 %0, t; }" : "=r"(a) : "l"(p));
  return a;
}
#define CP_ASYNC16(dst, src) \
  asm volatile("cp.async.cg.shared.global [%0], [%1], 16;" :: "r"(dst), "l"(src))
#define CP_COMMIT() asm volatile("cp.async.commit_group;" ::: "memory")
#define CP_WAIT1() asm volatile("cp.async.wait_group 1;" ::: "memory")
#define CP_WAIT0() asm volatile("cp.async.wait_group 0;" ::: "memory")

__device__ __forceinline__ void ldsm4(uint32_t* r, uint32_t addr) {
  asm volatile("ldmatrix.sync.aligned.m8n8.x4.shared.b16 {%0,%1,%2,%3}, [%4];"
               : "=r"(r[0]), "=r"(r[1]), "=r"(r[2]), "=r"(r[3]) : "r"(addr));
}
__device__ __forceinline__ void mma_f16(float* d, const uint32_t* a, const uint32_t* b) {
  asm volatile("mma.sync.aligned.m16n8k16.row.col.f32.f16.f16.f32 "
               "{%0,%1,%2,%3}, {%4,%5,%6,%7}, {%8,%9}, {%0,%1,%2,%3};"
               : "+f"(d[0]), "+f"(d[1]), "+f"(d[2]), "+f"(d[3])
               : "r"(a[0]), "r"(a[1]), "r"(a[2]), "r"(a[3]), "r"(b[0]), "r"(b[1]));
}
__device__ __forceinline__ uint32_t pack_h2(float a, float b) {
  __half2 p{__float2half_rn(a), __float2half_rn(b)};
  return *(uint32_t*)&p;
}

// ---------------- RoPE table precompute ----------------------------------------
__global__ void rope_table_kernel() {
  int idx = blockIdx.x * blockDim.x + threadIdx.x;
  if (idx >= T_ * 64) return;
  int t = idx >> 6, j = idx & 63;
  const double lg = 9.210340371976184;
  float inv = (float)exp(-(double)j / 64.0 * lg);
  float f = (float)t * inv;
  double s, c;
  sincos((double)f, &s, &c);
  g_rope[idx * 2]     = (float)c;
  g_rope[idx * 2 + 1] = (float)s;
}

// ---------------- f32 -> fp16 hi/lo split (2 planes) ---------------------------
__global__ __launch_bounds__(256) void split2_kernel(const float* __restrict__ X,
                                                     __half* __restrict__ Hh,
                                                     __half* __restrict__ Ll, int n4) {
  int i = blockIdx.x * blockDim.x + threadIdx.x;
  if (i >= n4) return;
  float4 v = *(const float4*)(X + (size_t)i * 4);
  __half h0 = __float2half_rn(v.x), h1 = __float2half_rn(v.y);
  __half h2 = __float2half_rn(v.z), h3 = __float2half_rn(v.w);
  __half2 hp0{h0, h1}, hp1{h2, h3};
  __half2 lp0{__float2half_rn(v.x - __half2float(h0)), __float2half_rn(v.y - __half2float(h1))};
  __half2 lp1{__float2half_rn(v.z - __half2float(h2)), __float2half_rn(v.w - __half2float(h3))};
  *(uint2*)(Hh + (size_t)i * 4) = make_uint2(*(uint32_t*)&hp0, *(uint32_t*)&hp1);
  *(uint2*)(Ll + (size_t)i * 4) = make_uint2(*(uint32_t*)&lp0, *(uint32_t*)&lp1);
}

// ---------------- all four weight truncations in one launch --------------------
#define N4_WQ (DIM_*DIM_/4)
#define N4_WK (KVD_*DIM_/4)
__global__ __launch_bounds__(256) void trunc_all_kernel(
    const float* __restrict__ Wq, const float* __restrict__ Wk,
    const float* __restrict__ Wv, const float* __restrict__ Wp,
    __half* __restrict__ wq, __half* __restrict__ wk,
    __half* __restrict__ wv, __half* __restrict__ wp) {
  int i = blockIdx.x * blockDim.x + threadIdx.x;
  const float* src; __half* dst; int off;
  if (i < N4_WQ)                     { src = Wq; dst = wq; off = i; }
  else if (i < N4_WQ + N4_WK)        { src = Wk; dst = wk; off = i - N4_WQ; }
  else if (i < N4_WQ + 2 * N4_WK)    { src = Wv; dst = wv; off = i - N4_WQ - N4_WK; }
  else                               { src = Wp; dst = wp; off = i - N4_WQ - 2 * N4_WK; }
  float4 v = *(const float4*)(src + (size_t)off * 4);
  __half2 hp0{__float2half_rn(v.x), __float2half_rn(v.y)};
  __half2 hp1{__float2half_rn(v.z), __float2half_rn(v.w)};
  *(uint2*)(dst + (size_t)off * 4) = make_uint2(*(uint32_t*)&hp0, *(uint32_t*)&hp1);
}

// ---------------- merged Q/K/V HMMA GEMM (one launch) --------------------------
#define GT (128 * 64 * 2)
#define SMEM_HG (2 * 3 * GT)              // 96KB
#define TSTR 134

__global__ __launch_bounds__(256, 2) void gemm_qkv(
    const __half* __restrict__ Ah, const __half* __restrict__ Al,
    const __half* __restrict__ Wq, const __half* __restrict__ Wk,
    const __half* __restrict__ Wv,
    __half* __restrict__ Qh, __half* __restrict__ Ql, __half* __restrict__ Kh,
    float* __restrict__ Vf, __half* __restrict__ Vt,
    const float* __restrict__ gain) {
  extern __shared__ char sm[];
  const uint32_t sb = smem_u32(sm);
  const int tid = threadIdx.x;
  const int l = tid & 31, w = tid >> 5;
  const int gx = blockIdx.x;
  const int bm = blockIdx.y * 128;
  const int wm = (w & 1) * 64, wn = (w >> 1) * 32;
  const int K = DIM_;

  int mode, bn;
  const __half* Bp;
  int N;
  if (gx < 16)      { mode = 0; bn = gx * 128;        Bp = Wq; N = DIM_; }
  else if (gx < 20) { mode = 1; bn = (gx - 16) * 128; Bp = Wk; N = KVD_; }
  else              { mode = 2; bn = (gx - 20) * 128; Bp = Wv; N = KVD_; }

  int ldrow[4]; uint32_t lddst[4]; int ldkoff[4];
#pragma unroll
  for (int s = 0; s < 4; s++) {
    int ch = tid + s * 256;
    ldrow[s] = ch >> 3;
    int kcol = ch & 7;
    lddst[s] = (uint32_t)(ldrow[s] * 128 + ((kcol * 16) ^ ((ldrow[s] & 7) << 4)));
    ldkoff[s] = kcol;
  }
  const int arow = (l & 7) + ((l >> 3) & 1) * 8;
  const int akb  = (l >> 4) * 16;
  const int brow = (l & 7) + (l >> 4) * 8;
  const int bkb  = ((l >> 3) & 1) * 16;
  const int kxor = (l & 7) << 4;
  int aoff[4], boff[2];
#pragma unroll
  for (int i = 0; i < 4; i++) aoff[i] = (wm + i * 16 + arow) * 128;
#pragma unroll
  for (int j = 0; j < 2; j++) boff[j] = (wn + j * 16 + brow) * 128;

  float acc[4][4][4];
#pragma unroll
  for (int i = 0; i < 4; i++)
#pragma unroll
    for (int j = 0; j < 4; j++)
#pragma unroll
      for (int r = 0; r < 4; r++) acc[i][j][r] = 0.f;

  const int NC = K / 64;

#define ISSUE_CHUNK(cc, buf) do {                                              \
    uint32_t base = sb + (buf) * 3 * GT;                                       \
    const __half* srcs[3] = {Ah, Al, Bp};                                      \
    _Pragma("unroll")                                                          \
    for (int tile = 0; tile < 3; tile++) {                                     \
      int rb = (tile < 2) ? bm : bn;                                           \
      const __half* sp = srcs[tile];                                           \
      _Pragma("unroll")                                                        \
      for (int s = 0; s < 4; s++) {                                            \
        const __half* src = sp + (size_t)(rb + ldrow[s]) * K +                 \
                            (cc) * 64 + ldkoff[s] * 8;                         \
        CP_ASYNC16(base + tile * GT + lddst[s], src);                          \
      }                                                                        \
    }                                                                          \
    CP_COMMIT();                                                               \
  } while (0)

  ISSUE_CHUNK(0, 0);

  for (int c = 0; c < NC; c++) {
    const int buf = c & 1;
    if (c + 1 < NC) { ISSUE_CHUNK(c + 1, buf ^ 1); CP_WAIT1(); }
    else            { CP_WAIT0(); }
    __syncthreads();

    const uint32_t tb = sb + buf * 3 * GT;
#pragma unroll
    for (int kc = 0; kc < 4; kc++) {
      uint32_t ah[4][4], al[4][4], bh[2][4];
      const uint32_t kA = (uint32_t)((kc * 32 + akb) ^ kxor);
      const uint32_t kB = (uint32_t)((kc * 32 + bkb) ^ kxor);
#pragma unroll
      for (int i = 0; i < 4; i++) {
        ldsm4(ah[i], tb + aoff[i] + kA);
        ldsm4(al[i], tb + GT + aoff[i] + kA);
      }
#pragma unroll
      for (int j = 0; j < 2; j++)
        ldsm4(bh[j], tb + 2 * GT + boff[j] + kB);
#pragma unroll
      for (int i = 0; i < 4; i++)
#pragma unroll
        for (int jf = 0; jf < 4; jf++) {
          const uint32_t* bph = &bh[jf >> 1][(jf & 1) * 2];
          mma_f16(acc[i][jf], ah[i], bph);
          mma_f16(acc[i][jf], al[i], bph);
        }
    }
    __syncthreads();
  }
#undef ISSUE_CHUNK

  const int r0 = bm + wm + (l >> 2);
  const int c0 = bn + wn + (l & 3) * 2;

  if (mode == 2) {
#pragma unroll
    for (int i = 0; i < 4; i++)
#pragma unroll
      for (int j = 0; j < 4; j++) {
        float* p0 = Vf + (size_t)(r0 + i * 16) * N + c0 + j * 8;
        float* p1 = Vf + (size_t)(r0 + i * 16 + 8) * N + c0 + j * 8;
        *(float2*)p0 = make_float2(acc[i][j][0], acc[i][j][1]);
        *(float2*)p1 = make_float2(acc[i][j][2], acc[i][j][3]);
      }
  }

  float* tile = (float*)sm;
  const int rl = wm + (l >> 2);
  const int cl = wn + (l & 3) * 2;
#pragma unroll
  for (int i = 0; i < 4; i++)
#pragma unroll
    for (int j = 0; j < 4; j++) {
      tile[(rl + i * 16) * TSTR + cl + j * 8]     = acc[i][j][0];
      tile[(rl + i * 16) * TSTR + cl + j * 8 + 1] = acc[i][j][1];
      tile[(rl + i * 16 + 8) * TSTR + cl + j * 8]     = acc[i][j][2];
      tile[(rl + i * 16 + 8) * TSTR + cl + j * 8 + 1] = acc[i][j][3];
    }
  __syncthreads();

  if (mode < 2) {
    const float gn = (mode == 0) ? gain[bn >> 7] : 1.f;
    __half* Oh = (mode == 0) ? Qh : Kh;
    __half* Ol = (mode == 0) ? Ql : nullptr;
#pragma unroll 1
    for (int it = 0; it < 16; it++) {
      int r = w * 16 + it;
      int grow = bm + r;
      int t = grow & (T_ - 1);
      float2 x1 = *(float2*)&tile[r * TSTR + l * 2];
      float2 x2 = *(float2*)&tile[r * TSTR + 64 + l * 2];
      float ss = x1.x*x1.x + x1.y*x1.y + x2.x*x2.x + x2.y*x2.y;
#pragma unroll
      for (int o = 16; o > 0; o >>= 1) ss += __shfl_xor_sync(0xffffffffu, ss, o);
      float gm = gn * rsqrtf(ss * (1.f / HD_) + EPS_);
      x1.x *= gm; x1.y *= gm; x2.x *= gm; x2.y *= gm;
      float4 cs = *(const float4*)(g_rope + (size_t)t * 128 + l * 4);
      float o1x = x1.x * cs.x - x2.x * cs.y;
      float o1y = x1.y * cs.z - x2.y * cs.w;
      float o2x = x2.x * cs.x + x1.x * cs.y;
      float o2y = x2.y * cs.z + x1.y * cs.w;
      size_t base = (size_t)grow * N + bn;
      __half h1a = __float2half_rn(o1x), h1b = __float2half_rn(o1y);
      __half h2a = __float2half_rn(o2x), h2b = __float2half_rn(o2y);
      __half2 hp1{h1a, h1b}, hp2{h2a, h2b};
      *(uint32_t*)(Oh + base + l * 2)      = *(uint32_t*)&hp1;
      *(uint32_t*)(Oh + base + 64 + l * 2) = *(uint32_t*)&hp2;
      if (Ol != nullptr) {
        __half2 lp1{__float2half_rn(o1x - __half2float(h1a)),
                    __float2half_rn(o1y - __half2float(h1b))};
        __half2 lp2{__float2half_rn(o2x - __half2float(h2a)),
                    __float2half_rn(o2y - __half2float(h2b))};
        *(uint32_t*)(Ol + base + l * 2)      = *(uint32_t*)&lp1;
        *(uint32_t*)(Ol + base + 64 + l * 2) = *(uint32_t*)&lp2;
      }
    }
  } else {
    const int b = bm >> 10, t0 = bm & (T_ - 1);
    const int kv = bn >> 7;
    const size_t vbase = ((size_t)(b * NKV_ + kv) * HD_) * T_;
#pragma unroll 1
    for (int it = 0; it < 16; it++) {
      int d = w * 16 + it;
      float v0 = tile[(l * 4 + 0) * TSTR + d];
      float v1 = tile[(l * 4 + 1) * TSTR + d];
      float v2 = tile[(l * 4 + 2) * TSTR + d];
      float v3 = tile[(l * 4 + 3) * TSTR + d];
      __half2 p0{__float2half_rn(v0), __float2half_rn(v1)};
      __half2 p1{__float2half_rn(v2), __float2half_rn(v3)};
      *(uint2*)(Vt + vbase + (size_t)d * T_ + t0 + l * 4) =
          make_uint2(*(uint32_t*)&p0, *(uint32_t*)&p1);
    }
  }
}

// ---------------- proj GEMM (128x128, single A-plane) --------------------------
__global__ __launch_bounds__(256, 2) void gemm_proj(
    const __half* __restrict__ Ah, const __half* __restrict__ Bh,
    float* __restrict__ C, int N, int K) {
  extern __shared__ char sm[];
  const uint32_t sb = smem_u32(sm);
  const int tid = threadIdx.x;
  const int l = tid & 31, w = tid >> 5;
  const int bm = blockIdx.y * 128, bn = blockIdx.x * 128;
  const int wm = (w & 1) * 64, wn = (w >> 1) * 32;

  int ldrow[4]; uint32_t lddst[4]; int ldkoff[4];
#pragma unroll
  for (int s = 0; s < 4; s++) {
    int ch = tid + s * 256;
    ldrow[s] = ch >> 3;
    int kcol = ch & 7;
    lddst[s] = (uint32_t)(ldrow[s] * 128 + ((kcol * 16) ^ ((ldrow[s] & 7) << 4)));
    ldkoff[s] = kcol;
  }
  const int arow = (l & 7) + ((l >> 3) & 1) * 8;
  const int akb  = (l >> 4) * 16;
  const int brow = (l & 7) + (l >> 4) * 8;
  const int bkb  = ((l >> 3) & 1) * 16;
  const int kxor = (l & 7) << 4;
  int aoff[4], boff[2];
#pragma unroll
  for (int i = 0; i < 4; i++) aoff[i] = (wm + i * 16 + arow) * 128;
#pragma unroll
  for (int j = 0; j < 2; j++) boff[j] = (wn + j * 16 + brow) * 128;

  float acc[4][4][4];
#pragma unroll
  for (int i = 0; i < 4; i++)
#pragma unroll
    for (int j = 0; j < 4; j++)
#pragma unroll
      for (int r = 0; r < 4; r++) acc[i][j][r] = 0.f;

  const int NC = K / 64;

#define ISSUE_P(cc, buf) do {                                                  \
    uint32_t base = sb + (buf) * 3 * GT;                                       \
    _Pragma("unroll")                                                          \
    for (int s = 0; s < 4; s++) {                                              \
      const __half* srcA = Ah + (size_t)(bm + ldrow[s]) * K +                  \
                           (cc) * 64 + ldkoff[s] * 8;                          \
      CP_ASYNC16(base + lddst[s], srcA);                                       \
      const __half* srcB = Bh + (size_t)(bn + ldrow[s]) * K +                  \
                           (cc) * 64 + ldkoff[s] * 8;                          \
      CP_ASYNC16(base + 2 * GT + lddst[s], srcB);                              \
    }                                                                          \
    CP_COMMIT();                                                               \
  } while (0)

  ISSUE_P(0, 0);

  for (int c = 0; c < NC; c++) {
    const int buf = c & 1;
    if (c + 1 < NC) { ISSUE_P(c + 1, buf ^ 1); CP_WAIT1(); }
    else            { CP_WAIT0(); }
    __syncthreads();

    const uint32_t tb = sb + buf * 3 * GT;
#pragma unroll
    for (int kc = 0; kc < 4; kc++) {
      uint32_t ah[4][4], bh[2][4];
      const uint32_t kA = (uint32_t)((kc * 32 + akb) ^ kxor);
      const uint32_t kB = (uint32_t)((kc * 32 + bkb) ^ kxor);
#pragma unroll
      for (int i = 0; i < 4; i++) ldsm4(ah[i], tb + aoff[i] + kA);
#pragma unroll
      for (int j = 0; j < 2; j++) ldsm4(bh[j], tb + 2 * GT + boff[j] + kB);
#pragma unroll
      for (int i = 0; i < 4; i++)
#pragma unroll
        for (int jf = 0; jf < 4; jf++)
          mma_f16(acc[i][jf], ah[i], &bh[jf >> 1][(jf & 1) * 2]);
    }
    __syncthreads();
  }
#undef ISSUE_P

  const int r0 = bm + wm + (l >> 2);
  const int c0 = bn + wn + (l & 3) * 2;
#pragma unroll
  for (int i = 0; i < 4; i++)
#pragma unroll
    for (int j = 0; j < 4; j++) {
      float* p0 = C + (size_t)(r0 + i * 16) * N + c0 + j * 8;
      float* p1 = C + (size_t)(r0 + i * 16 + 8) * N + c0 + j * 8;
      *(float2*)p0 = make_float2(acc[i][j][0], acc[i][j][1]);
      *(float2*)p1 = make_float2(acc[i][j][2], acc[i][j][3]);
    }
}

// ---------------- HMMA flash attention + fused v-rejection + trunc -------------
#define FQ_OFF   0
#define FBUF_OFF 65536
#define SMEM_FLA (65536 + 2 * 32768)
#define VSTR 136

__global__ __launch_bounds__(256, 1) void flash_hmma(
    const __half* __restrict__ Qh, const __half* __restrict__ Ql,
    const __half* __restrict__ Kh, const __half* __restrict__ Vth,
    const float* __restrict__ Vf,
    __half* __restrict__ Yh) {
  extern __shared__ char sm[];
  const uint32_t sb = smem_u32(sm);
  const int tid = threadIdx.x;
  const int l = tid & 31, w = tid >> 5;
  const int qtile = gridDim.x - 1 - blockIdx.x;
  const int bh = blockIdx.y;
  const int b = bh >> 4, h = bh & 15, kv = h >> 2;
  const int q0 = qtile * 128;
  const int wm = w * 16;

  const int arow = (l & 7) + ((l >> 3) & 1) * 8;
  const int akb  = (l >> 4) * 16;
  const int brow = (l & 7) + (l >> 4) * 8;
  const int bkb  = ((l >> 3) & 1) * 16;
  const uint32_t kxA = (uint32_t)((l & 7) << 4);

#pragma unroll
  for (int s = 0; s < 8; s++) {
    int ch = tid + s * 256;
    int kchunk = ch >> 10;
    int cid = ch & 1023;
    int r = cid >> 3, cc = cid & 7;
    uint32_t dst = (uint32_t)(kchunk * 16384 + r * 128 + ((cc * 16) ^ ((r & 7) << 4)));
    size_t src = (size_t)(b * T_ + q0 + r) * DIM_ + h * HD_ + kchunk * 64 + cc * 8;
    CP_ASYNC16(sb + FQ_OFF + dst, Qh + src);
    CP_ASYNC16(sb + FQ_OFF + 32768 + dst, Ql + src);
  }
  CP_COMMIT();

#define FKV_ISSUE(tt, buf) do {                                                 \
    uint32_t base = sb + FBUF_OFF + (buf) * 32768;                              \
    int s0_ = (tt) * 64;                                                        \
    _Pragma("unroll")                                                           \
    for (int s = 0; s < 4; s++) {                                               \
      int ch = tid + s * 256;                                                   \
      int kchunk = ch >> 9;                                                     \
      int cid = ch & 511;                                                       \
      int r = cid >> 3, cc = cid & 7;                                           \
      uint32_t dst = (uint32_t)(kchunk * 8192 + r * 128 +                       \
                                ((cc * 16) ^ ((r & 7) << 4)));                  \
      size_t src = (size_t)(b * T_ + s0_ + r) * KVD_ + kv * 128 +               \
                   kchunk * 64 + cc * 8;                                        \
      CP_ASYNC16(base + dst, Kh + src);                                         \
    }                                                                           \
    _Pragma("unroll")                                                           \
    for (int s = 0; s < 4; s++) {                                               \
      int ch = tid + s * 256;                                                   \
      int r = ch >> 3, cc = ch & 7;                                             \
      uint32_t dst = (uint32_t)(r * 128 + ((cc * 16) ^ ((r & 7) << 4)));        \
      size_t src = ((size_t)(b * 4 + kv) * 128 + r) * T_ + s0_ + cc * 8;        \
      CP_ASYNC16(base + 16384 + dst, Vth + src);                                \
    }                                                                           \
    CP_COMMIT();                                                                \
  } while (0)

  const int nt = (q0 + 128) / 64;
  FKV_ISSUE(0, 0);

  float ys[16][4];
#pragma unroll
  for (int i = 0; i < 16; i++)
#pragma unroll
    for (int r = 0; r < 4; r++) ys[i][r] = 0.f;
  float m0 = -INFINITY, m1 = -INFINITY, l0 = 0.f, l1 = 0.f;
  const int rg0 = q0 + wm + (l >> 2);
  const int wrow_max = q0 + wm + 15;

  for (int t = 0; t < nt; t++) {
    const int buf = t & 1;
    if (t + 1 < nt) { FKV_ISSUE(t + 1, buf ^ 1); CP_WAIT1(); }
    else            { CP_WAIT0(); }
    __syncthreads();

    const int s0 = t * 64;
    if (s0 <= wrow_max) {
      const uint32_t KB = sb + FBUF_OFF + buf * 32768;
      const uint32_t VB = KB + 16384;
      float sacc[8][4];
#pragma unroll
      for (int j = 0; j < 8; j++)
#pragma unroll
        for (int r = 0; r < 4; r++) sacc[j][r] = 0.f;

#pragma unroll
      for (int ks = 0; ks < 8; ks++) {
        const int kchunk = ks >> 2, kc = ks & 3;
        uint32_t ah[4], al[4];
        uint32_t qa = sb + FQ_OFF + kchunk * 16384 + (wm + arow) * 128 +
                      (((kc * 32 + akb)) ^ kxA);
        ldsm4(ah, qa);
        ldsm4(al, qa + 32768);
#pragma unroll
        for (int j = 0; j < 4; j++) {
          uint32_t bh4[4];
          uint32_t ka = KB + kchunk * 8192 + (j * 16 + brow) * 128 +
                        (((kc * 32 + bkb)) ^ kxA);
          ldsm4(bh4, ka);
          mma_f16(sacc[2 * j],     ah, &bh4[0]);
          mma_f16(sacc[2 * j],     al, &bh4[0]);
          mma_f16(sacc[2 * j + 1], ah, &bh4[2]);
          mma_f16(sacc[2 * j + 1], al, &bh4[2]);
        }
      }

#pragma unroll
      for (int j = 0; j < 8; j++) {
        int cg = s0 + j * 8 + (l & 3) * 2;
        sacc[j][0] = (cg     <= rg0)     ? sacc[j][0] * SCALE_ : -INFINITY;
        sacc[j][1] = (cg + 1 <= rg0)     ? sacc[j][1] * SCALE_ : -INFINITY;
        sacc[j][2] = (cg     <= rg0 + 8) ? sacc[j][2] * SCALE_ : -INFINITY;
        sacc[j][3] = (cg + 1 <= rg0 + 8) ? sacc[j][3] * SCALE_ : -INFINITY;
      }
      float rm0 = -INFINITY, rm1 = -INFINITY;
#pragma unroll
      for (int j = 0; j < 8; j++) {
        rm0 = fmaxf(rm0, fmaxf(sacc[j][0], sacc[j][1]));
        rm1 = fmaxf(rm1, fmaxf(sacc[j][2], sacc[j][3]));
      }
      rm0 = fmaxf(rm0, __shfl_xor_sync(0xffffffffu, rm0, 1));
      rm0 = fmaxf(rm0, __shfl_xor_sync(0xffffffffu, rm0, 2));
      rm1 = fmaxf(rm1, __shfl_xor_sync(0xffffffffu, rm1, 1));
      rm1 = fmaxf(rm1, __shfl_xor_sync(0xffffffffu, rm1, 2));
      float nm0 = fmaxf(m0, rm0), nm1 = fmaxf(m1, rm1);
      float a0 = expf(m0 - nm0), a1 = expf(m1 - nm1);
      m0 = nm0; m1 = nm1;
      l0 *= a0; l1 *= a1;
#pragma unroll
      for (int i = 0; i < 16; i++) {
        ys[i][0] *= a0; ys[i][1] *= a0; ys[i][2] *= a1; ys[i][3] *= a1;
      }
#pragma unroll
      for (int j = 0; j < 8; j++) {
        sacc[j][0] = expf(sacc[j][0] - nm0);
        sacc[j][1] = expf(sacc[j][1] - nm0);
        sacc[j][2] = expf(sacc[j][2] - nm1);
        sacc[j][3] = expf(sacc[j][3] - nm1);
        l0 += sacc[j][0] + sacc[j][1];
        l1 += sacc[j][2] + sacc[j][3];
      }

#pragma unroll
      for (int u = 0; u < 4; u++) {
        uint32_t pha[4];
        pha[0] = pack_h2(sacc[2*u][0], sacc[2*u][1]);
        pha[1] = pack_h2(sacc[2*u][2], sacc[2*u][3]);
        pha[2] = pack_h2(sacc[2*u+1][0], sacc[2*u+1][1]);
        pha[3] = pack_h2(sacc[2*u+1][2], sacc[2*u+1][3]);
#pragma unroll
        for (int jj = 0; jj < 8; jj++) {
          uint32_t vh4[4];
          uint32_t va = VB + (jj * 16 + brow) * 128 + (((u * 32 + bkb)) ^ kxA);
          ldsm4(vh4, va);
          mma_f16(ys[2 * jj],     pha, &vh4[0]);
          mma_f16(ys[2 * jj + 1], pha, &vh4[2]);
        }
      }
    }
    __syncthreads();
  }
#undef FKV_ISSUE

  l0 += __shfl_xor_sync(0xffffffffu, l0, 1);
  l0 += __shfl_xor_sync(0xffffffffu, l0, 2);
  l1 += __shfl_xor_sync(0xffffffffu, l1, 1);
  l1 += __shfl_xor_sync(0xffffffffu, l1, 2);
  const float i0 = 1.f / l0, i1 = 1.f / l1;

  float* vs = (float*)sm;
  __syncthreads();
#pragma unroll
  for (int s = 0; s < 16; s++) {
    int idx = tid + s * 256;
    int r = idx >> 5, c4 = (idx & 31) << 2;
    *(float4*)&vs[r * VSTR + c4] =
        *(const float4*)(Vf + (size_t)(b * T_ + q0 + r) * KVD_ + kv * 128 + c4);
  }
  __syncthreads();

  const int lr0 = wm + (l >> 2), lr1 = lr0 + 8;
  float ss0 = 0.f, ss1 = 0.f;
#pragma unroll
  for (int tt = 0; tt < 16; tt++) {
    int c = tt * 8 + (l & 3) * 2;
    float2 a = *(float2*)&vs[lr0 * VSTR + c];
    float2 bb = *(float2*)&vs[lr1 * VSTR + c];
    ss0 += a.x * a.x + a.y * a.y;
    ss1 += bb.x * bb.x + bb.y * bb.y;
  }
  ss0 += __shfl_xor_sync(0xffffffffu, ss0, 1);
  ss0 += __shfl_xor_sync(0xffffffffu, ss0, 2);
  ss1 += __shfl_xor_sync(0xffffffffu, ss1, 1);
  ss1 += __shfl_xor_sync(0xffffffffu, ss1, 2);
  const float inv0 = 1.f / (sqrtf(ss0) + 1e-8f);
  const float inv1 = 1.f / (sqrtf(ss1) + 1e-8f);

  float dot0 = 0.f, dot1 = 0.f;
#pragma unroll
  for (int tt = 0; tt < 16; tt++) {
    int c = tt * 8 + (l & 3) * 2;
    float2 a = *(float2*)&vs[lr0 * VSTR + c];
    float2 bb = *(float2*)&vs[lr1 * VSTR + c];
    ys[tt][0] *= i0; ys[tt][1] *= i0; ys[tt][2] *= i1; ys[tt][3] *= i1;
    dot0 += ys[tt][0] * a.x + ys[tt][1] * a.y;
    dot1 += ys[tt][2] * bb.x + ys[tt][3] * bb.y;
  }
  dot0 += __shfl_xor_sync(0xffffffffu, dot0, 1);
  dot0 += __shfl_xor_sync(0xffffffffu, dot0, 2);
  dot1 += __shfl_xor_sync(0xffffffffu, dot1, 1);
  dot1 += __shfl_xor_sync(0xffffffffu, dot1, 2);
  const float s0c = dot0 * inv0 * inv0;
  const float s1c = dot1 * inv1 * inv1;

#pragma unroll
  for (int tt = 0; tt < 16; tt++) {
    int c = tt * 8 + (l & 3) * 2;
    float2 a = *(float2*)&vs[lr0 * VSTR + c];
    float2 bb = *(float2*)&vs[lr1 * VSTR + c];
    float o00 = ys[tt][0] - s0c * a.x;
    float o01 = ys[tt][1] - s0c * a.y;
    float o10 = ys[tt][2] - s1c * bb.x;
    float o11 = ys[tt][3] - s1c * bb.y;
    size_t off0 = (size_t)(b * T_ + rg0) * DIM_ + h * HD_ + c;
    size_t off1 = (size_t)(b * T_ + rg0 + 8) * DIM_ + h * HD_ + c;
    __half2 hp0{__float2half_rn(o00), __float2half_rn(o01)};
    __half2 hp1{__float2half_rn(o10), __float2half_rn(o11)};
    *(uint32_t*)(Yh + off0) = *(uint32_t*)&hp0;
    *(uint32_t*)(Yh + off1) = *(uint32_t*)&hp1;
  }
}

// ---------------- launch ------------------------------------------------------
extern "C" void kernel_launch(void* const* d_in, const int* in_sizes, int n_in,
                              void* d_out, int out_size) {
  const float* x     = (const float*)d_in[0];
  const float* Wq    = (const float*)d_in[1];
  const float* Wk    = (const float*)d_in[2];
  const float* Wv    = (const float*)d_in[3];
  const float* Wproj = (const float*)d_in[4];
  const float* qgain = (const float*)d_in[5];
  float* out = (float*)d_out;

  float *vb;
  cudaGetSymbolAddress((void**)&vb, g_v);
  __half *xh, *xl, *wq, *wk, *wv, *wp, *qh, *ql, *kh, *vth;
  cudaGetSymbolAddress((void**)&xh, g_xh);
  cudaGetSymbolAddress((void**)&xl, g_xl);
  cudaGetSymbolAddress((void**)&wq, g_wq);
  cudaGetSymbolAddress((void**)&wk, g_wk);
  cudaGetSymbolAddress((void**)&wv, g_wv);
  cudaGetSymbolAddress((void**)&wp, g_wp);
  cudaGetSymbolAddress((void**)&qh, g_qh);
  cudaGetSymbolAddress((void**)&ql, g_ql);
  cudaGetSymbolAddress((void**)&kh, g_kh);
  cudaGetSymbolAddress((void**)&vth, g_vth);

  cudaFuncSetAttribute((void*)gemm_qkv, cudaFuncAttributeMaxDynamicSharedMemorySize, SMEM_HG);
  cudaFuncSetAttribute((void*)gemm_proj, cudaFuncAttributeMaxDynamicSharedMemorySize, SMEM_HG);
  cudaFuncSetAttribute((void*)flash_hmma, cudaFuncAttributeMaxDynamicSharedMemorySize, SMEM_FLA);

  const int M = B_ * T_;

  rope_table_kernel<<<(T_ * 64 + 255) / 256, 256>>>();
  split2_kernel<<<(M * DIM_ / 4 + 255) / 256, 256>>>(x, xh, xl, M * DIM_ / 4);
  const int n4all = 2 * N4_WQ + 2 * N4_WK;
  trunc_all_kernel<<<(n4all + 255) / 256, 256>>>(Wq, Wk, Wv, Wproj, wq, wk, wv, wp);

  dim3 gqkv(24, M / 128);
  gemm_qkv<<<gqkv, 256, SMEM_HG>>>(xh, xl, wq, wk, wv, qh, ql, kh, vb, vth, qgain);

  dim3 gf(T_ / 128, B_ * H_);
  flash_hmma<<<gf, 256, SMEM_FLA>>>(qh, ql, kh, vth, vb, xh);

  dim3 gbig(DIM_ / 128, M / 128);
  gemm_proj<<<gbig, 256, SMEM_HG>>>(xh, wp, out, DIM_, DIM_);
}